// round 6
// baseline (speedup 1.0000x reference)
#include <cuda_runtime.h>

typedef unsigned long long u64;

#define KNB   16
#define FIN   7
#define FHID  40
#define FOUT  3
#define TILE  128
#define NF4   28          // float4 per node (16*7 floats)
#define HPG   5           // hidden pairs per register group
#define NGRP  4           // 4 groups x 5 hp = 20 hp = 40 hidden
#define HP    20

// ---- packed f32x2 helpers ----
__device__ __forceinline__ u64 pk2(float lo, float hi) {
    u64 r; asm("mov.b64 %0, {%1,%2};" : "=l"(r) : "f"(lo), "f"(hi)); return r;
}
__device__ __forceinline__ void upk2(u64 v, float& lo, float& hi) {
    asm("mov.b64 {%0,%1}, %2;" : "=f"(lo), "=f"(hi) : "l"(v));
}
__device__ __forceinline__ u64 ffma2(u64 a, u64 b, u64 c) {
    u64 d; asm("fma.rn.f32x2 %0, %1, %2, %3;" : "=l"(d) : "l"(a), "l"(b), "l"(c)); return d;
}
__device__ __forceinline__ u64 fadd2(u64 a, u64 b) {
    u64 d; asm("add.rn.f32x2 %0, %1, %2;" : "=l"(d) : "l"(a), "l"(b)); return d;
}
__device__ __forceinline__ unsigned smem_u32(const void* p) {
    unsigned a;
    asm("{ .reg .u64 t; cvta.to.shared.u64 t, %1; cvt.u32.u64 %0, t; }" : "=r"(a) : "l"(p));
    return a;
}
__device__ __forceinline__ void cp_async16(unsigned dst, const void* src) {
    asm volatile("cp.async.cg.shared.global [%0], [%1], 16;" :: "r"(dst), "l"(src));
}

// smem layout (dynamic):
//   s_x4[NF4][TILE]  float4   -- transposed tile: granule (j*128+i) => per-phase
//                                banks are i&7 for lanes 0..7 => conflict-free,
//                                no padding needed (448B/node exactly)
//   s_w1[HP][8]      float2   -- 7 weight pairs + bias pair per hidden-pair
//   s_w2[HP][3]      float2   -- (W2[2hp][o], W2[2hp+1][o])
//   s_b2[4]          float
#define SMEM_X_F4   (NF4 * TILE)
#define SMEM_BYTES  (SMEM_X_F4 * 16 + HP * 8 * 8 + HP * 3 * 8 + 16)

__global__ __launch_bounds__(128, 3)
void aggre_kernel(const float* __restrict__ mailbox,
                  const float* __restrict__ W1,
                  const float* __restrict__ b1,
                  const float* __restrict__ W2,
                  const float* __restrict__ b2,
                  float* __restrict__ out,
                  int n_nodes)
{
    extern __shared__ __align__(16) float4 smem4[];
    float4* s_x  = smem4;
    u64*    s_w1 = reinterpret_cast<u64*>(s_x + SMEM_X_F4);   // [HP*8] float2-as-u64
    u64*    s_w2 = s_w1 + HP * 8;                              // [HP*3]
    float*  s_b2 = reinterpret_cast<float*>(s_w2 + HP * FOUT);

    const int tid   = threadIdx.x;
    const int nbase = blockIdx.x * TILE;
    const int nval  = min(TILE, n_nodes - nbase);

    // ---- stage weights as hidden-pair float2 (no duplication needed) ----
    for (int i = tid; i < HP * 8; i += 128) {
        int hp = i >> 3, f = i & 7;
        float lo, hi;
        if (f < FIN) { lo = W1[f * FHID + 2 * hp]; hi = W1[f * FHID + 2 * hp + 1]; }
        else         { lo = b1[2 * hp];            hi = b1[2 * hp + 1]; }
        s_w1[i] = pk2(lo, hi);
    }
    for (int i = tid; i < HP * FOUT; i += 128) {
        int hp = i / FOUT, o = i - hp * FOUT;
        s_w2[i] = pk2(W2[(2 * hp) * FOUT + o], W2[(2 * hp + 1) * FOUT + o]);
    }
    if (tid < FOUT) s_b2[tid] = b2[tid];

    // ---- stage mailbox tile TRANSPOSED: s_x[j][i] = node i, float4 j ----
    {
        const float4* src = reinterpret_cast<const float4*>(mailbox) + (size_t)nbase * NF4;
        unsigned xb = smem_u32(s_x);
        if (nval == TILE) {
            #pragma unroll
            for (int it = 0; it < NF4; it++) {
                int g = it * 128 + tid;      // linear over (i, j), j fastest
                int i = g / NF4;
                int j = g - i * NF4;
                cp_async16(xb + (unsigned)(j * TILE + i) * 16u, src + g);
            }
        } else {
            int total = nval * NF4;
            for (int it = 0; it < NF4; it++) {
                int g = it * 128 + tid;
                if (g < total) {
                    int i = g / NF4;
                    int j = g - i * NF4;
                    cp_async16(xb + (unsigned)(j * TILE + i) * 16u, src + g);
                }
            }
        }
        asm volatile("cp.async.commit_group;");
        asm volatile("cp.async.wait_group 0;");
    }
    __syncthreads();

    // ---- per-node compute: f32x2 lanes = (hidden 2hp, hidden 2hp+1) ----
    if (nbase + tid < n_nodes) {
        const float4* xcol = s_x + tid;     // column for this node

        u64 y[FOUT] = {0ULL, 0ULL, 0ULL};

        #pragma unroll 1
        for (int grp = 0; grp < NGRP; grp++) {
            // resident weights for 5 hidden-pairs (40 u64 = 80 regs)
            u64 w[HPG][FIN], bp[HPG];
            #pragma unroll
            for (int h = 0; h < HPG; h++) {
                const ulonglong2* row =
                    reinterpret_cast<const ulonglong2*>(s_w1 + (grp * HPG + h) * 8);
                ulonglong2 p0 = row[0], p1 = row[1], p2 = row[2], p3 = row[3];
                w[h][0] = p0.x; w[h][1] = p0.y; w[h][2] = p1.x; w[h][3] = p1.y;
                w[h][4] = p2.x; w[h][5] = p2.y; w[h][6] = p3.x; bp[h] = p3.y;
            }

            u64 hs[HPG] = {0ULL, 0ULL, 0ULL, 0ULL, 0ULL};

            #pragma unroll
            for (int kc = 0; kc < 4; kc++) {          // 4 chunks x 4 messages
                // 7 conflict-free LDS.128 (transposed layout), then lane-dup
                float4 v[7];
                #pragma unroll
                for (int t = 0; t < 7; t++) v[t] = xcol[(kc * 7 + t) * TILE];

                u64 xd[28];
                #pragma unroll
                for (int t = 0; t < 7; t++) {
                    xd[4 * t + 0] = pk2(v[t].x, v[t].x);
                    xd[4 * t + 1] = pk2(v[t].y, v[t].y);
                    xd[4 * t + 2] = pk2(v[t].z, v[t].z);
                    xd[4 * t + 3] = pk2(v[t].w, v[t].w);
                }

                #pragma unroll
                for (int h = 0; h < HPG; h++) {
                    #pragma unroll
                    for (int j = 0; j < 4; j++) {
                        u64 a = bp[h];
                        #pragma unroll
                        for (int f = 0; f < FIN; f++)
                            a = ffma2(xd[7 * j + f], w[h][f], a);
                        float ax, ay; upk2(a, ax, ay);
                        hs[h] = fadd2(hs[h], pk2(fmaxf(ax, 0.f), fmaxf(ay, 0.f)));
                    }
                }
            }

            // fold group's hidden sums into packed outputs
            #pragma unroll
            for (int h = 0; h < HPG; h++) {
                int hp = grp * HPG + h;
                #pragma unroll
                for (int o = 0; o < FOUT; o++)
                    y[o] = ffma2(hs[h], s_w2[hp * FOUT + o], y[o]);
            }
        }

        const float inv = 1.0f / 16.0f;
        float* op = out + (size_t)(nbase + tid) * FOUT;
        #pragma unroll
        for (int o = 0; o < FOUT; o++) {
            float lo, hi; upk2(y[o], lo, hi);
            op[o] = fmaf(lo + hi, inv, s_b2[o]);
        }
    }
}

extern "C" void kernel_launch(void* const* d_in, const int* in_sizes, int n_in,
                              void* d_out, int out_size)
{
    const float* mailbox = (const float*)d_in[0];
    const float* W1      = (const float*)d_in[1];
    const float* b1      = (const float*)d_in[2];
    const float* W2      = (const float*)d_in[3];
    const float* b2      = (const float*)d_in[4];
    float* out = (float*)d_out;

    int n_nodes = in_sizes[0] / (KNB * FIN);
    int blocks  = (n_nodes + TILE - 1) / TILE;

    cudaFuncSetAttribute(aggre_kernel,
                         cudaFuncAttributeMaxDynamicSharedMemorySize, SMEM_BYTES);
    aggre_kernel<<<blocks, 128, SMEM_BYTES>>>(mailbox, W1, b1, W2, b2, out, n_nodes);
}

// round 7
// speedup vs baseline: 1.1837x; 1.1837x over previous
#include <cuda_runtime.h>

typedef unsigned long long u64;

#define KNB   16
#define FIN   7
#define FHID  40
#define FOUT  3
#define HP    20          // hidden pairs (40/2)
#define HPG   4           // hidden pairs per register group
#define NGRP  5           // 5 groups x 4 hp
#define TILE  160         // nodes per block == threads per block
#define THREADS 160
#define NF4   28          // float4 per node (16*7 floats)
#define STR   29          // padded float4 stride in smem (odd -> conflict-free LDS.128)

// ---- packed f32x2 helpers ----
__device__ __forceinline__ u64 pk2(float lo, float hi) {
    u64 r; asm("mov.b64 %0, {%1,%2};" : "=l"(r) : "f"(lo), "f"(hi)); return r;
}
__device__ __forceinline__ void upk2(u64 v, float& lo, float& hi) {
    asm("mov.b64 {%0,%1}, %2;" : "=f"(lo), "=f"(hi) : "l"(v));
}
__device__ __forceinline__ u64 ffma2(u64 a, u64 b, u64 c) {
    u64 d; asm("fma.rn.f32x2 %0, %1, %2, %3;" : "=l"(d) : "l"(a), "l"(b), "l"(c)); return d;
}
__device__ __forceinline__ u64 fadd2(u64 a, u64 b) {
    u64 d; asm("add.rn.f32x2 %0, %1, %2;" : "=l"(d) : "l"(a), "l"(b)); return d;
}
__device__ __forceinline__ unsigned smem_u32(const void* p) {
    unsigned a;
    asm("{ .reg .u64 t; cvta.to.shared.u64 t, %1; cvt.u32.u64 %0, t; }" : "=r"(a) : "l"(p));
    return a;
}
__device__ __forceinline__ void cp_async16(unsigned dst, const void* src) {
    asm volatile("cp.async.cg.shared.global [%0], [%1], 16;" :: "r"(dst), "l"(src));
}

// smem: s_x[TILE][STR] float4 (padded rows), s_w1[HP][8] f2, s_w2[HP][3] f2, s_b2
#define SMEM_X_F4   (TILE * STR)
#define SMEM_BYTES  (SMEM_X_F4 * 16 + HP * 8 * 8 + HP * 3 * 8 + 16)

// process 2 messages (msgA = 2 consecutive msgs) against the 4 resident hp
__device__ __forceinline__ void do2msgs(const u64 xd[14], const u64 w[HPG][FIN],
                                        const u64 bp[HPG], u64 hs[HPG])
{
    #pragma unroll
    for (int h = 0; h < HPG; h++) {
        #pragma unroll
        for (int j = 0; j < 2; j++) {
            u64 a = bp[h];
            #pragma unroll
            for (int f = 0; f < FIN; f++)
                a = ffma2(xd[7 * j + f], w[h][f], a);
            float ax, ay; upk2(a, ax, ay);
            hs[h] = fadd2(hs[h], pk2(fmaxf(ax, 0.f), fmaxf(ay, 0.f)));
        }
    }
}

__global__ __launch_bounds__(THREADS, 3)
void aggre_kernel(const float* __restrict__ mailbox,
                  const float* __restrict__ W1,
                  const float* __restrict__ b1,
                  const float* __restrict__ W2,
                  const float* __restrict__ b2,
                  float* __restrict__ out,
                  int n_nodes)
{
    extern __shared__ __align__(16) float4 smem4[];
    float4* s_x  = smem4;
    u64*    s_w1 = reinterpret_cast<u64*>(s_x + SMEM_X_F4);   // [HP*8]
    u64*    s_w2 = s_w1 + HP * 8;                              // [HP*3]
    float*  s_b2 = reinterpret_cast<float*>(s_w2 + HP * FOUT);

    const int tid   = threadIdx.x;
    const int nbase = blockIdx.x * TILE;
    const int nval  = min(TILE, n_nodes - nbase);

    // ---- stage weights as hidden-pair float2 ----
    for (int i = tid; i < HP * 8; i += THREADS) {
        int hp = i >> 3, f = i & 7;
        float lo, hi;
        if (f < FIN) { lo = W1[f * FHID + 2 * hp]; hi = W1[f * FHID + 2 * hp + 1]; }
        else         { lo = b1[2 * hp];            hi = b1[2 * hp + 1]; }
        s_w1[i] = pk2(lo, hi);
    }
    for (int i = tid; i < HP * FOUT; i += THREADS) {
        int hp = i / FOUT, o = i - hp * FOUT;
        s_w2[i] = pk2(W2[(2 * hp) * FOUT + o], W2[(2 * hp + 1) * FOUT + o]);
    }
    if (tid < FOUT) s_b2[tid] = b2[tid];

    // ---- stage mailbox tile: coalesced cp.async into padded rows ----
    {
        const float4* src = reinterpret_cast<const float4*>(mailbox) + (size_t)nbase * NF4;
        unsigned xb = smem_u32(s_x);
        if (nval == TILE) {
            #pragma unroll
            for (int it = 0; it < NF4; it++) {          // 28 iters x 160 threads
                int g = it * THREADS + tid;
                int i = g / NF4;
                int j = g - i * NF4;
                cp_async16(xb + (unsigned)(i * STR + j) * 16u, src + g);
            }
        } else {
            int total = nval * NF4;
            for (int it = 0; it < NF4; it++) {
                int g = it * THREADS + tid;
                if (g < total) {
                    int i = g / NF4;
                    int j = g - i * NF4;
                    cp_async16(xb + (unsigned)(i * STR + j) * 16u, src + g);
                }
            }
        }
        asm volatile("cp.async.commit_group;");
        asm volatile("cp.async.wait_group 0;");
    }
    __syncthreads();

    // ---- per-node compute: f32x2 lanes = (hidden 2hp, hidden 2hp+1) ----
    if (nbase + tid < n_nodes) {
        const float4* xrow = s_x + tid * STR;

        u64 y[FOUT] = {0ULL, 0ULL, 0ULL};

        #pragma unroll 1
        for (int grp = 0; grp < NGRP; grp++) {
            // resident weights for 4 hidden-pairs (32 u64 = 64 regs)
            u64 w[HPG][FIN], bp[HPG];
            #pragma unroll
            for (int h = 0; h < HPG; h++) {
                const ulonglong2* row =
                    reinterpret_cast<const ulonglong2*>(s_w1 + (grp * HPG + h) * 8);
                ulonglong2 p0 = row[0], p1 = row[1], p2 = row[2], p3 = row[3];
                w[h][0] = p0.x; w[h][1] = p0.y; w[h][2] = p1.x; w[h][3] = p1.y;
                w[h][4] = p2.x; w[h][5] = p2.y; w[h][6] = p3.x; bp[h] = p3.y;
            }

            u64 hs[HPG] = {0ULL, 0ULL, 0ULL, 0ULL};

            #pragma unroll
            for (int kc = 0; kc < 4; kc++) {          // 4 chunks x 4 messages
                // ---- half 1: msgs 0,1 of chunk (floats 0..13) ----
                float4 v0 = xrow[kc * 7 + 0];
                float4 v1 = xrow[kc * 7 + 1];
                float4 v2 = xrow[kc * 7 + 2];
                float4 v3 = xrow[kc * 7 + 3];
                float c14 = v3.z, c15 = v3.w;          // msg2 f0,f1 carried
                {
                    u64 xd[14];
                    xd[0] = pk2(v0.x, v0.x); xd[1] = pk2(v0.y, v0.y);
                    xd[2] = pk2(v0.z, v0.z); xd[3] = pk2(v0.w, v0.w);
                    xd[4] = pk2(v1.x, v1.x); xd[5] = pk2(v1.y, v1.y);
                    xd[6] = pk2(v1.z, v1.z);
                    xd[7] = pk2(v1.w, v1.w); xd[8]  = pk2(v2.x, v2.x);
                    xd[9] = pk2(v2.y, v2.y); xd[10] = pk2(v2.z, v2.z);
                    xd[11] = pk2(v2.w, v2.w); xd[12] = pk2(v3.x, v3.x);
                    xd[13] = pk2(v3.y, v3.y);
                    do2msgs(xd, w, bp, hs);
                }
                // ---- half 2: msgs 2,3 of chunk (floats 14..27) ----
                float4 v4 = xrow[kc * 7 + 4];
                float4 v5 = xrow[kc * 7 + 5];
                float4 v6 = xrow[kc * 7 + 6];
                {
                    u64 xd[14];
                    xd[0] = pk2(c14, c14);   xd[1] = pk2(c15, c15);
                    xd[2] = pk2(v4.x, v4.x); xd[3] = pk2(v4.y, v4.y);
                    xd[4] = pk2(v4.z, v4.z); xd[5] = pk2(v4.w, v4.w);
                    xd[6] = pk2(v5.x, v5.x);
                    xd[7] = pk2(v5.y, v5.y); xd[8]  = pk2(v5.z, v5.z);
                    xd[9] = pk2(v5.w, v5.w); xd[10] = pk2(v6.x, v6.x);
                    xd[11] = pk2(v6.y, v6.y); xd[12] = pk2(v6.z, v6.z);
                    xd[13] = pk2(v6.w, v6.w);
                    do2msgs(xd, w, bp, hs);
                }
            }

            // fold group's hidden sums into packed outputs
            #pragma unroll
            for (int h = 0; h < HPG; h++) {
                int hp = grp * HPG + h;
                #pragma unroll
                for (int o = 0; o < FOUT; o++)
                    y[o] = ffma2(hs[h], s_w2[hp * FOUT + o], y[o]);
            }
        }

        const float inv = 1.0f / 16.0f;
        float* op = out + (size_t)(nbase + tid) * FOUT;
        #pragma unroll
        for (int o = 0; o < FOUT; o++) {
            float lo, hi; upk2(y[o], lo, hi);
            op[o] = fmaf(lo + hi, inv, s_b2[o]);
        }
    }
}

extern "C" void kernel_launch(void* const* d_in, const int* in_sizes, int n_in,
                              void* d_out, int out_size)
{
    const float* mailbox = (const float*)d_in[0];
    const float* W1      = (const float*)d_in[1];
    const float* b1      = (const float*)d_in[2];
    const float* W2      = (const float*)d_in[3];
    const float* b2      = (const float*)d_in[4];
    float* out = (float*)d_out;

    int n_nodes = in_sizes[0] / (KNB * FIN);
    int blocks  = (n_nodes + TILE - 1) / TILE;

    cudaFuncSetAttribute(aggre_kernel,
                         cudaFuncAttributeMaxDynamicSharedMemorySize, SMEM_BYTES);
    aggre_kernel<<<blocks, THREADS, SMEM_BYTES>>>(mailbox, W1, b1, W2, b2, out, n_nodes);
}